// round 14
// baseline (speedup 1.0000x reference)
#include <cuda_runtime.h>
#include <cuda_bf16.h>
#include <cstdint>

// Problem shapes (fixed for this dataset entry)
constexpr int B = 4;
constexpr int S = 4096;
constexpr int D = 2048;
constexpr int HALO  = 8;
constexpr int NROWS = 2048;
constexpr int NTOK  = B * S;          // 16384
constexpr int CAP   = 32;             // slots per row (Poisson mean 8)

constexpr int PRE_THREADS = 256;      // 8 warps; warp covers 24 tokens
constexpr int PRE_BLOCKS  = 86;       // ceil(ceil(16384/24)/8)

constexpr int FB_BLOCKS = NTOK / 512; // 32 fallback blocks

// Device scratch (no allocs; g_cnt zero-initialized, reset by out_kernel)
__device__ float    g_w[NTOK * HALO];
__device__ unsigned g_flag[NTOK];
__device__ int      g_cnt[NROWS];
__device__ int      g_order[NROWS * CAP];
__device__ int      g_pos[NTOK];

// ---------------------------------------------------------------------------
// Pre-kernel: per-token weight DP (warp-shuffle) + slot assignment.
//   w^k[j] = w^{k-1}[j] + p[t-k] * w^{k-1}_nb[j-1],  w_0 == 1 implicit;
//   p[s] = (x[s] >= 16) && (x[s+1] < 16), valid only inside the token's batch.
//   Lane = token; influence moves 1 lane/level => lanes >= 8 exact.
// ---------------------------------------------------------------------------
__global__ __launch_bounds__(PRE_THREADS)
void pre_kernel(const int* __restrict__ x)
{
    const int wid  = threadIdx.x >> 5;
    const int lane = threadIdx.x & 31;

    const int W  = blockIdx.x * 8 + wid;      // global warp id
    const int tf = W * 24 - 8 + lane;         // token (lanes < 8: halo)
    const bool valid = (lane >= HALO) && (tf >= 0) && (tf < NTOK);

    int xs[9];                                // x[tf-8 .. tf] (clamped)
#pragma unroll
    for (int i = 0; i < 9; i++) {
        int s = tf - 8 + i;
        s = max(0, min(s, NTOK - 1));
        xs[i] = x[s];
    }
    const int xv = xs[8];

    unsigned pm = 0;                          // bit k: p[tf-k] != 0
    if (tf >= 0 && tf < NTOK) {
        const int bstart = tf & ~(S - 1);     // batch start (linear layout)
#pragma unroll
        for (int k = 1; k <= 8; k++) {
            const int s = tf - k;
            if (s >= bstart && xs[8 - k] >= 16 && xs[9 - k] < 16)
                pm |= (1u << k);
        }
    }

    float wj[HALO];
#pragma unroll
    for (int j = 0; j < HALO; j++) wj[j] = 0.0f;
#pragma unroll
    for (int k = 1; k <= 8; k++) {
        const float pv = (pm >> k) & 1u ? 1.0f : 0.0f;
        float nb[HALO - 1];
#pragma unroll
        for (int j = 0; j < HALO - 1; j++)
            nb[j] = __shfl_up_sync(0xFFFFFFFFu, wj[j], 1);
        float nb0 = 1.0f;
        if (lane == 0) {
            nb0 = 0.0f;
#pragma unroll
            for (int j = 0; j < HALO - 1; j++) nb[j] = 0.0f;
        }
        wj[0] = fmaf(pv, nb0, wj[0]);
#pragma unroll
        for (int j = 1; j < HALO; j++) wj[j] = fmaf(pv, nb[j - 1], wj[j]);
    }

    if (valid) {
        unsigned m = 0;
#pragma unroll
        for (int j = 0; j < HALO; j++) {
            if (wj[j] != 0.0f) m |= (1u << (j + 1));
            g_w[(size_t)tf * HALO + j] = wj[j];
        }
        g_flag[tf] = m;
        const int pos = atomicAdd(&g_cnt[xv], 1);
        g_pos[tf] = pos;
        if (pos < CAP) g_order[xv * CAP + pos] = tf;
    }
}

// ---------------------------------------------------------------------------
// Output kernel.
//  Blocks [0, NROWS): one block per emb row. Load row once into registers,
//  stream to each destination token; slow tokens (flag != 0) corrected inline:
//     out[t] = e[x[t]] + sum_j w_j(t) * e[x[t-j]]
//  Resets g_cnt[r] after use (replay-safe).
//  Blocks [NROWS, NROWS+FB_BLOCKS): overflow fallback — tokens whose slot
//  position >= CAP get the full formula directly (normally none).
// ---------------------------------------------------------------------------
__global__ __launch_bounds__(512)
void out_kernel(const int* __restrict__ x,
                const float* __restrict__ emb,
                float* __restrict__ out)
{
    const int tid = threadIdx.x;

    if (blockIdx.x < NROWS) {
        const int r = blockIdx.x;
        __shared__ int      socc[CAP];
        __shared__ unsigned sfl[CAP];
        __shared__ int      sn;

        if (tid == 0) {
            sn = min(g_cnt[r], CAP);
            g_cnt[r] = 0;                 // reset for next replay
        }
        __syncthreads();
        const int n = sn;
        if (n == 0) return;

        if (tid < n) {
            const int idx = g_order[r * CAP + tid];
            socc[tid] = idx;
            sfl[tid]  = g_flag[idx];
        }
        __syncthreads();

        const float4 e = *reinterpret_cast<const float4*>(
            emb + (size_t)r * D + tid * 4);

        for (int k = 0; k < n; k++) {
            float4 c = e;
            const unsigned m = sfl[k];
            if (m) {
                const int tf = socc[k];
#pragma unroll
                for (int j = 1; j <= HALO; j++) {
                    if ((m >> j) & 1u) {
                        // bit j set => w_j != 0 => t-j stays inside this sequence
                        const float  w  = __ldg(&g_w[(size_t)tf * HALO + (j - 1)]);
                        const int    rj = __ldg(&x[tf - j]);
                        const float4 h  = *reinterpret_cast<const float4*>(
                            emb + (size_t)rj * D + tid * 4);
                        c.x = fmaf(h.x, w, c.x);
                        c.y = fmaf(h.y, w, c.y);
                        c.z = fmaf(h.z, w, c.z);
                        c.w = fmaf(h.w, w, c.w);
                    }
                }
            }
            __stcs(reinterpret_cast<float4*>(
                out + (size_t)socc[k] * D + tid * 4), c);
        }
    } else {
        // ---- overflow fallback (normally a fast no-op) ----
        const int base = (blockIdx.x - NROWS) * 512;
        __shared__ int psh[512];
        __shared__ int any;
        if (tid == 0) any = 0;
        __syncthreads();
        const int p = g_pos[base + tid];
        psh[tid] = p;
        if (p >= CAP) atomicAdd(&any, 1);
        __syncthreads();
        if (any == 0) return;

        for (int k = 0; k < 512; k++) {
            if (psh[k] >= CAP) {
                const int tf = base + k;
                const unsigned m = g_flag[tf];
                float4 c = *reinterpret_cast<const float4*>(
                    emb + (size_t)x[tf] * D + tid * 4);
#pragma unroll
                for (int j = 1; j <= HALO; j++) {
                    if ((m >> j) & 1u) {
                        const float  w  = __ldg(&g_w[(size_t)tf * HALO + (j - 1)]);
                        const int    rj = __ldg(&x[tf - j]);
                        const float4 h  = *reinterpret_cast<const float4*>(
                            emb + (size_t)rj * D + tid * 4);
                        c.x = fmaf(h.x, w, c.x);
                        c.y = fmaf(h.y, w, c.y);
                        c.z = fmaf(h.z, w, c.z);
                        c.w = fmaf(h.w, w, c.w);
                    }
                }
                __stcs(reinterpret_cast<float4*>(
                    out + (size_t)tf * D + tid * 4), c);
            }
        }
    }
}

extern "C" void kernel_launch(void* const* d_in, const int* in_sizes, int n_in,
                              void* d_out, int out_size)
{
    const int*   x   = (const int*)d_in[0];
    const float* emb = (const float*)d_in[1];
    float*       out = (float*)d_out;

    pre_kernel<<<PRE_BLOCKS, PRE_THREADS>>>(x);
    out_kernel<<<NROWS + FB_BLOCKS, 512>>>(x, emb, out);
}

// round 15
// speedup vs baseline: 1.2950x; 1.2950x over previous
#include <cuda_runtime.h>
#include <cuda_bf16.h>
#include <cstdint>

// Problem shapes (fixed for this dataset entry)
constexpr int B = 4;
constexpr int S = 4096;
constexpr int D = 2048;
constexpr int HALO  = 8;
constexpr int NROWS = 2048;
constexpr int NTOK  = B * S;          // 16384
constexpr int CHUNK = 16;             // tokens per output block
constexpr int NCHUNK = NTOK / CHUNK;  // 1024

constexpr int PREP_BLOCKS  = 64;      // block b owns tokens [256b, 256b+256)
constexpr int PREP_THREADS = 256;

// Device scratch (no allocs; fully overwritten every launch -> replay-safe)
__device__ float    g_w[NTOK * HALO];
__device__ unsigned g_flag[NTOK];
__device__ int      g_order[NTOK];

// ---------------------------------------------------------------------------
// Prep kernel: self-contained per block (no cross-block communication).
//  1) stream x -> smem hist_full + hist_before (tokens with index < base)
//  2) block-local exclusive scan of hist_full -> global row offsets
//     cursor[r] = excl[r] + before[r]  (this block's start within row r's span)
//  3) scatter own 256 tokens into g_order (disjoint, exactly-tiling ranges)
//  4) warp-shuffle weight DP for own tokens -> g_w, g_flag
//     w^k[j] = w^{k-1}[j] + p[t-k] * w^{k-1}_nb[j-1],  w_0 == 1 implicit;
//     p[s] = (x[s] >= 16) && (x[s+1] < 16), valid only inside the token's batch.
//     Lane = token; influence moves 1 lane/level => lanes >= 8 exact.
// ---------------------------------------------------------------------------
__global__ __launch_bounds__(PREP_THREADS)
void prep_kernel(const int* __restrict__ x)
{
    const int tid  = threadIdx.x;
    const int wid  = tid >> 5;
    const int lane = tid & 31;
    const int base = blockIdx.x * PREP_THREADS;

    __shared__ int hfull[NROWS];
    __shared__ int hbef[NROWS];
    __shared__ int wsums[8];

    for (int i = tid; i < NROWS; i += PREP_THREADS) {
        hfull[i] = 0;
        hbef[i]  = 0;
    }
    __syncthreads();

    // ---- 1) histogram of all tokens + "before my range" histogram ----
    for (int i = tid; i < NTOK; i += PREP_THREADS) {
        const int v = x[i];
        atomicAdd(&hfull[v], 1);
        if (i < base) atomicAdd(&hbef[v], 1);
    }
    __syncthreads();

    // ---- 2) exclusive scan of hfull (2048 bins, 8 per thread) ----
    const int b8 = tid * 8;
    int v[8], pre[8];
    int run = 0;
#pragma unroll
    for (int j = 0; j < 8; j++) {
        v[j]  = hfull[b8 + j];
        pre[j] = run;
        run  += v[j];
    }
    int incl = run;
#pragma unroll
    for (int off = 1; off < 32; off <<= 1) {
        const int n = __shfl_up_sync(0xFFFFFFFFu, incl, off);
        if (lane >= off) incl += n;
    }
    if (lane == 31) wsums[wid] = incl;
    __syncthreads();
    if (wid == 0) {
        const int wv = (lane < 8) ? wsums[lane] : 0;
        int wincl = wv;
#pragma unroll
        for (int off = 1; off < 8; off <<= 1) {
            const int n = __shfl_up_sync(0xFFFFFFFFu, wincl, off);
            if (lane >= off) wincl += n;
        }
        if (lane < 8) wsums[lane] = wincl - wv;       // exclusive warp base
    }
    __syncthreads();
    const int tbase = wsums[wid] + (incl - run);       // excl prefix at b8
#pragma unroll
    for (int j = 0; j < 8; j++) {
        const int idx = b8 + j;                        // thread-exclusive bins
        hbef[idx] = tbase + pre[j] + hbef[idx];        // -> this block's cursor
    }
    __syncthreads();

    // ---- 3) scatter own token (order within a row is arbitrary) ----
    {
        const int i  = base + tid;
        const int xv = x[i];
        const int pos = atomicAdd(&hbef[xv], 1);
        g_order[pos] = i;
    }

    // ---- 4) weight DP: 16 groups of 24 net tokens; groups 0..10 cover 256 ----
#pragma unroll
    for (int p = 0; p < 2; p++) {
        const int g = wid + p * 8;
        if (g > 10) continue;
        const int tf = base + g * 24 - 8 + lane;       // lanes < 8: halo
        const bool valid = (lane >= HALO) && (g * 24 + lane - 8) < PREP_THREADS
                           && tf < NTOK;

        int xs[9];                                     // x[tf-8 .. tf] clamped
#pragma unroll
        for (int i = 0; i < 9; i++) {
            int s = tf - 8 + i;
            s = max(0, min(s, NTOK - 1));
            xs[i] = x[s];
        }
        unsigned pm = 0;                               // bit k: p[tf-k] != 0
        if (tf >= 0 && tf < NTOK) {
            const int bstart = tf & ~(S - 1);          // batch start (linear)
#pragma unroll
            for (int k = 1; k <= 8; k++) {
                const int s = tf - k;
                if (s >= bstart && xs[8 - k] >= 16 && xs[9 - k] < 16)
                    pm |= (1u << k);
            }
        }

        float wj[HALO];
#pragma unroll
        for (int j = 0; j < HALO; j++) wj[j] = 0.0f;
#pragma unroll
        for (int k = 1; k <= 8; k++) {
            const float pv = (pm >> k) & 1u ? 1.0f : 0.0f;
            float nb[HALO - 1];
#pragma unroll
            for (int j = 0; j < HALO - 1; j++)
                nb[j] = __shfl_up_sync(0xFFFFFFFFu, wj[j], 1);
            float nb0 = 1.0f;
            if (lane == 0) {
                nb0 = 0.0f;
#pragma unroll
                for (int j = 0; j < HALO - 1; j++) nb[j] = 0.0f;
            }
            wj[0] = fmaf(pv, nb0, wj[0]);
#pragma unroll
            for (int j = 1; j < HALO; j++) wj[j] = fmaf(pv, nb[j - 1], wj[j]);
        }

        if (valid) {
            unsigned m = 0;
#pragma unroll
            for (int j = 0; j < HALO; j++) {
                if (wj[j] != 0.0f) m |= (1u << (j + 1));
                g_w[(size_t)tf * HALO + j] = wj[j];
            }
            g_flag[tf] = m;
        }
    }
}

// ---------------------------------------------------------------------------
// Output kernel (Round-12 version, verbatim — 27.3 us measured).
//  Block = 16 row-grouped tokens; row held in registers, reloaded only on
//  (block-uniform) row change. Slow tokens (flag != 0) corrected inline:
//     out[t] = e[x[t]] + sum_j w_j(t) * e[x[t-j]]
//  Correctness does not depend on g_order's ordering.
// ---------------------------------------------------------------------------
__global__ __launch_bounds__(512)
void out_kernel(const int* __restrict__ x,
                const float* __restrict__ emb,
                float* __restrict__ out)
{
    const int tid = threadIdx.x;
    const int c0  = blockIdx.x * CHUNK;

    __shared__ int      socc[CHUNK];
    __shared__ int      srow[CHUNK];
    __shared__ unsigned sfl[CHUNK];

    if (tid < CHUNK) {
        const int idx = g_order[c0 + tid];
        socc[tid] = idx;
        srow[tid] = __ldg(&x[idx]);
        sfl[tid]  = g_flag[idx];
    }
    __syncthreads();

    float4 e = make_float4(0.f, 0.f, 0.f, 0.f);
    int cur = -1;

    for (int k = 0; k < CHUNK; k++) {
        const int r = srow[k];                       // block-uniform
        if (r != cur) {
            e = *reinterpret_cast<const float4*>(emb + (size_t)r * D + tid * 4);
            cur = r;
        }
        float4 c = e;
        const unsigned m = sfl[k];
        if (m) {
            const int tf = socc[k];
#pragma unroll
            for (int j = 1; j <= HALO; j++) {
                if ((m >> j) & 1u) {
                    // bit j set => w_j != 0 => t-j stays inside this sequence
                    const float  w  = __ldg(&g_w[(size_t)tf * HALO + (j - 1)]);
                    const int    rj = __ldg(&x[tf - j]);
                    const float4 h  = *reinterpret_cast<const float4*>(
                        emb + (size_t)rj * D + tid * 4);
                    c.x = fmaf(h.x, w, c.x);
                    c.y = fmaf(h.y, w, c.y);
                    c.z = fmaf(h.z, w, c.z);
                    c.w = fmaf(h.w, w, c.w);
                }
            }
        }
        __stcs(reinterpret_cast<float4*>(out + (size_t)socc[k] * D + tid * 4), c);
    }
}

extern "C" void kernel_launch(void* const* d_in, const int* in_sizes, int n_in,
                              void* d_out, int out_size)
{
    const int*   x   = (const int*)d_in[0];
    const float* emb = (const float*)d_in[1];
    float*       out = (float*)d_out;

    prep_kernel<<<PREP_BLOCKS, PREP_THREADS>>>(x);
    out_kernel<<<NCHUNK, 512>>>(x, emb, out);
}